// round 15
// baseline (speedup 1.0000x reference)
#include <cuda_runtime.h>
#include <cuda_fp16.h>
#include <cstdint>

// out[b,n,m,0]=cos(src_n,tgt_m), out[b,n,m,1]=1/(1+||src_n-tgt_m||)
// dot via 2-pass split-fp16 mma.sync: hiA*hiB + hiA*loB, fp32 accumulate.

#define NN 2048
#define CC 128
#define ROWSZ (4 * NN)

__device__ __half g_hiS[ROWSZ * CC];
__device__ __half g_hiT[ROWSZ * CC];
__device__ __half g_loT[ROWSZ * CC];
__device__ float2 g_nS[ROWSZ];   // {|s|^2, 1/max(|s|,eps)}
__device__ float2 g_nT[ROWSZ];

// ---------------------------------------------------------------------------
// prep: fp32 -> fp16 hi (+ lo for tgt only) + fused row norms. Warp per row.
// ---------------------------------------------------------------------------
__global__ void prep(const float* __restrict__ S, const float* __restrict__ T) {
    int gw = (blockIdx.x * blockDim.x + threadIdx.x) >> 5;
    int lane = threadIdx.x & 31;
    if (gw >= ROWSZ) return;
    bool ist = (blockIdx.y != 0);
    const float* p = (ist ? T : S) + (size_t)gw * CC + lane * 4;
    float4 v = *(const float4*)p;
    float sq = v.x * v.x + v.y * v.y + v.z * v.z + v.w * v.w;
#pragma unroll
    for (int o = 16; o; o >>= 1) sq += __shfl_xor_sync(0xffffffffu, sq, o);

    __half2 h01 = __floats2half2_rn(v.x, v.y);
    __half2 h23 = __floats2half2_rn(v.z, v.w);

    size_t off = (size_t)gw * CC + lane * 4;
    if (ist) {
        float2 f01 = __half22float2(h01);
        float2 f23 = __half22float2(h23);
        __half2 l01 = __floats2half2_rn(v.x - f01.x, v.y - f01.y);
        __half2 l23 = __floats2half2_rn(v.z - f23.x, v.w - f23.y);
        *(uint2*)(g_hiT + off) = make_uint2(*(uint32_t*)&h01, *(uint32_t*)&h23);
        *(uint2*)(g_loT + off) = make_uint2(*(uint32_t*)&l01, *(uint32_t*)&l23);
    } else {
        *(uint2*)(g_hiS + off) = make_uint2(*(uint32_t*)&h01, *(uint32_t*)&h23);
    }
    if (lane == 0) {
        float2 nv;
        nv.x = sq;
        nv.y = 1.0f / fmaxf(sqrtf(sq), 1e-12f);
        (ist ? g_nT : g_nS)[gw] = nv;
    }
}

// ---------------------------------------------------------------------------
__device__ __forceinline__ uint32_t s2u(const void* p) {
    uint32_t a;
    asm("{ .reg .u64 t; cvta.to.shared.u64 t, %1; cvt.u32.u64 %0, t; }" : "=r"(a) : "l"(p));
    return a;
}
// Full-K tile: 128 rows x 128 halfs = 256 B/row. 16B granule kg 0..15,
// slot = kg ^ (row&7)  ->  bank-group (slot&7) distinct across any 8-row
// ldmatrix phase and across the 16 granules of a cp.async store row.
// K-step XOR property: addr(row, 2*kk+g0) = addr(row, g0) ^ (kk<<5).
__device__ __forceinline__ uint32_t toff(int row, int kg) {
    return (uint32_t)((row << 8) + ((kg ^ (row & 7)) << 4));
}
__device__ __forceinline__ void cpasync16(uint32_t s, const void* g) {
    asm volatile("cp.async.cg.shared.global [%0], [%1], 16;" :: "r"(s), "l"(g) : "memory");
}
__device__ __forceinline__ void ldm4(uint32_t& r0, uint32_t& r1, uint32_t& r2,
                                     uint32_t& r3, uint32_t a) {
    asm volatile("ldmatrix.sync.aligned.m8n8.x4.shared.b16 {%0,%1,%2,%3}, [%4];"
                 : "=r"(r0), "=r"(r1), "=r"(r2), "=r"(r3) : "r"(a));
}
__device__ __forceinline__ void mma16816(float* c, const uint32_t* a, const uint32_t* b) {
    asm volatile(
        "mma.sync.aligned.m16n8k16.row.col.f32.f16.f16.f32 "
        "{%0,%1,%2,%3}, {%4,%5,%6,%7}, {%8,%9}, {%0,%1,%2,%3};"
        : "+f"(c[0]), "+f"(c[1]), "+f"(c[2]), "+f"(c[3])
        : "r"(a[0]), "r"(a[1]), "r"(a[2]), "r"(a[3]), "r"(b[0]), "r"(b[1]));
}
__device__ __forceinline__ float sqrt_ap(float x) { float r; asm("sqrt.approx.f32 %0,%1;" : "=f"(r) : "f"(x)); return r; }
__device__ __forceinline__ float rcp_ap(float x)  { float r; asm("rcp.approx.f32 %0,%1;"  : "=f"(r) : "f"(x)); return r; }

// ---------------------------------------------------------------------------
// CTA tile 128(n) x 128(m), 8 warps 2(n) x 4(m), warp tile 64x32.
// Single-shot smem: full K for {Ahi, Bhi, Blo} = 3 x 32 KB = 96 KB, ONE
// cp.async burst + ONE barrier. Compute is mi-pair-major: full K for output
// rows mi{0,1}, inline epilogue, then mi{2,3} (mma of group 2 overlaps
// group 1's MUFU/STG epilogue). 2 CTAs/SM.
// ---------------------------------------------------------------------------
#define OB_HI 32768
#define OB_LO 65536
#define SMEM_TOTAL 98304

__global__ __launch_bounds__(256, 2)
void simgemm(float* __restrict__ out) {
    extern __shared__ __align__(1024) char sm[];
    uint32_t sb = s2u(sm);
    const int tid = threadIdx.x, lane = tid & 31, w = tid >> 5;
    const int wm = w & 1, wn = w >> 1;      // wm: n-dir (2), wn: m-dir (4)
    const int b = blockIdx.z, bm = blockIdx.x, bn = blockIdx.y;
    const int aRow0 = b * NN + bn * 128;    // src rows (C rows, n)
    const int bRow0 = b * NN + bm * 128;    // tgt rows (C cols, m)

    // ---- one-shot loads: 24 cp.async per thread ----
    {
        const __half* gah = g_hiS + (size_t)aRow0 * CC;
        const __half* gbh = g_hiT + (size_t)bRow0 * CC;
        const __half* gbl = g_loT + (size_t)bRow0 * CC;
#pragma unroll
        for (int j = 0; j < 8; j++) {
            int g = tid + j * 256;
            int row = g >> 4, kg = g & 15;
            uint32_t o = toff(row, kg);
            size_t go = (size_t)row * CC + kg * 8;
            cpasync16(sb + o,         gah + go);
            cpasync16(sb + OB_HI + o, gbh + go);
            cpasync16(sb + OB_LO + o, gbl + go);
        }
        asm volatile("cp.async.commit_group;" ::: "memory");
    }

    // base ldmatrix offsets at kk=0; kk advance = ^(kk<<5)
    uint32_t aoff[4], boff[2];
    {
        int ar = (lane & 7) + ((lane >> 3) & 1) * 8;
        int akg = lane >> 4;                        // granule 0/1
#pragma unroll
        for (int mi = 0; mi < 4; mi++)
            aoff[mi] = toff(wm * 64 + mi * 16 + ar, akg);
        int br = (lane & 7) + (lane >> 4) * 8;
        int bkg = (lane >> 3) & 1;
#pragma unroll
        for (int nip = 0; nip < 2; nip++)
            boff[nip] = toff(wn * 32 + nip * 16 + br, bkg);
    }

    // hoisted m-column norms (constant across mi groups)
    const int q = lane >> 2;
    const int mp = (lane & 3) * 2;
    float2 nt0v[4], nt1v[4];
#pragma unroll
    for (int ni = 0; ni < 4; ni++) {
        int m0 = bm * 128 + wn * 32 + ni * 8 + mp;
        nt0v[ni] = g_nT[b * NN + m0];
        nt1v[ni] = g_nT[b * NN + m0 + 1];
    }

    asm volatile("cp.async.wait_group 0;" ::: "memory");
    __syncthreads();

    // ---- mi-pair groups: K-loop then inline epilogue ----
#pragma unroll
    for (int mip = 0; mip < 2; mip++) {
        float acc[2][4][4];
#pragma unroll
        for (int i = 0; i < 2; i++)
#pragma unroll
            for (int j = 0; j < 4; j++)
#pragma unroll
                for (int k = 0; k < 4; k++) acc[i][j][k] = 0.0f;

        uint32_t a0b = aoff[mip * 2], a1b = aoff[mip * 2 + 1];

#pragma unroll
        for (int kk = 0; kk < 8; kk++) {
            const uint32_t x = (uint32_t)(kk << 5);
            uint32_t bf[4][2], a0[4], a1[4];
#pragma unroll
            for (int nip = 0; nip < 2; nip++)
                ldm4(bf[nip * 2][0], bf[nip * 2][1], bf[nip * 2 + 1][0],
                     bf[nip * 2 + 1][1], sb + OB_HI + (boff[nip] ^ x));
            ldm4(a0[0], a0[1], a0[2], a0[3], sb + (a0b ^ x));
            ldm4(a1[0], a1[1], a1[2], a1[3], sb + (a1b ^ x));
            // hi x hi
#pragma unroll
            for (int ni = 0; ni < 4; ni++) {
                mma16816(acc[0][ni], a0, bf[ni]);
                mma16816(acc[1][ni], a1, bf[ni]);
            }
            // reload bf <- lo (reuse regs)
#pragma unroll
            for (int nip = 0; nip < 2; nip++)
                ldm4(bf[nip * 2][0], bf[nip * 2][1], bf[nip * 2 + 1][0],
                     bf[nip * 2 + 1][1], sb + OB_LO + (boff[nip] ^ x));
            // hi x lo
#pragma unroll
            for (int ni = 0; ni < 4; ni++) {
                mma16816(acc[0][ni], a0, bf[ni]);
                mma16816(acc[1][ni], a1, bf[ni]);
            }
        }

        // ---- epilogue for this mi pair ----
#pragma unroll
        for (int i = 0; i < 2; i++) {
            int mi = mip * 2 + i;
            int n0 = bn * 128 + wm * 64 + mi * 16 + q;
            float2 ns0 = g_nS[b * NN + n0];
            float2 ns1 = g_nS[b * NN + n0 + 8];
            float* r0 = out + (((size_t)(b * NN + n0)) * NN) * 2;
            float* r1 = out + (((size_t)(b * NN + n0 + 8)) * NN) * 2;
#pragma unroll
            for (int ni = 0; ni < 4; ni++) {
                int m0 = bm * 128 + wn * 32 + ni * 8 + mp;
                float2 nt0 = nt0v[ni];
                float2 nt1 = nt1v[ni];
                const float* cc = acc[i][ni];

                float cs00 = cc[0] * ns0.y * nt0.y;
                float cs01 = cc[1] * ns0.y * nt1.y;
                float cs10 = cc[2] * ns1.y * nt0.y;
                float cs11 = cc[3] * ns1.y * nt1.y;
                float fd00 = rcp_ap(1.0f + sqrt_ap(fmaxf(ns0.x + nt0.x - 2.0f * cc[0], 0.0f)));
                float fd01 = rcp_ap(1.0f + sqrt_ap(fmaxf(ns0.x + nt1.x - 2.0f * cc[1], 0.0f)));
                float fd10 = rcp_ap(1.0f + sqrt_ap(fmaxf(ns1.x + nt0.x - 2.0f * cc[2], 0.0f)));
                float fd11 = rcp_ap(1.0f + sqrt_ap(fmaxf(ns1.x + nt1.x - 2.0f * cc[3], 0.0f)));

                *(float4*)(r0 + (size_t)m0 * 2) = make_float4(cs00, fd00, cs01, fd01);
                *(float4*)(r1 + (size_t)m0 * 2) = make_float4(cs10, fd10, cs11, fd11);
            }
        }
    }
}

// ---------------------------------------------------------------------------
extern "C" void kernel_launch(void* const* d_in, const int* in_sizes, int n_in,
                              void* d_out, int out_size) {
    const float* src = (const float*)d_in[0];
    const float* tgt = (const float*)d_in[1];
    float* out = (float*)d_out;
    (void)in_sizes; (void)n_in; (void)out_size;

    cudaFuncSetAttribute(simgemm, cudaFuncAttributeMaxDynamicSharedMemorySize,
                         SMEM_TOTAL);
    prep<<<dim3(1024, 2, 1), 256>>>(src, tgt);
    simgemm<<<dim3(16, 16, 4), 256, SMEM_TOTAL>>>(out);
}

// round 16
// speedup vs baseline: 1.3282x; 1.3282x over previous
#include <cuda_runtime.h>
#include <cuda_fp16.h>
#include <cstdint>

// out[b,n,m,0]=cos(src_n,tgt_m), out[b,n,m,1]=1/(1+||src_n-tgt_m||)
// dot via 2-pass split-fp16 mma.sync: hiA*hiB + hiA*loB, fp32 accumulate.
// Persistent work-stealing CTAs; cross-tile cp.async pipelining.

#define NN 2048
#define CC 128
#define ROWSZ (4 * NN)
#define NTILE 1024      // 16 x 16 x 4
#define NBLK 304        // 152 SMs x 2 CTAs

__device__ __half g_hiS[ROWSZ * CC];
__device__ __half g_hiT[ROWSZ * CC];
__device__ __half g_loT[ROWSZ * CC];
__device__ float2 g_nS[ROWSZ];   // {|s|^2, 1/max(|s|,eps)}
__device__ float2 g_nT[ROWSZ];
__device__ int g_ctr;            // work-stealing ticket (reset by prep)

// ---------------------------------------------------------------------------
// prep: fp32 -> fp16 hi (+ lo for tgt only) + fused row norms. Warp per row.
// Also resets the tile ticket each launch (graph-replay safe).
// ---------------------------------------------------------------------------
__global__ void prep(const float* __restrict__ S, const float* __restrict__ T) {
    if (blockIdx.x == 0 && blockIdx.y == 0 && threadIdx.x == 0) g_ctr = NBLK;
    int gw = (blockIdx.x * blockDim.x + threadIdx.x) >> 5;
    int lane = threadIdx.x & 31;
    if (gw >= ROWSZ) return;
    bool ist = (blockIdx.y != 0);
    const float* p = (ist ? T : S) + (size_t)gw * CC + lane * 4;
    float4 v = *(const float4*)p;
    float sq = v.x * v.x + v.y * v.y + v.z * v.z + v.w * v.w;
#pragma unroll
    for (int o = 16; o; o >>= 1) sq += __shfl_xor_sync(0xffffffffu, sq, o);

    __half2 h01 = __floats2half2_rn(v.x, v.y);
    __half2 h23 = __floats2half2_rn(v.z, v.w);

    size_t off = (size_t)gw * CC + lane * 4;
    if (ist) {
        float2 f01 = __half22float2(h01);
        float2 f23 = __half22float2(h23);
        __half2 l01 = __floats2half2_rn(v.x - f01.x, v.y - f01.y);
        __half2 l23 = __floats2half2_rn(v.z - f23.x, v.w - f23.y);
        *(uint2*)(g_hiT + off) = make_uint2(*(uint32_t*)&h01, *(uint32_t*)&h23);
        *(uint2*)(g_loT + off) = make_uint2(*(uint32_t*)&l01, *(uint32_t*)&l23);
    } else {
        *(uint2*)(g_hiS + off) = make_uint2(*(uint32_t*)&h01, *(uint32_t*)&h23);
    }
    if (lane == 0) {
        float2 nv;
        nv.x = sq;
        nv.y = 1.0f / fmaxf(sqrtf(sq), 1e-12f);
        (ist ? g_nT : g_nS)[gw] = nv;
    }
}

// ---------------------------------------------------------------------------
__device__ __forceinline__ uint32_t s2u(const void* p) {
    uint32_t a;
    asm("{ .reg .u64 t; cvta.to.shared.u64 t, %1; cvt.u32.u64 %0, t; }" : "=r"(a) : "l"(p));
    return a;
}
// Tile = 128 rows x 64 halfs (128 B/row), classic SW128 8x8 swizzle:
// offset = row*128 + ((kg ^ (row&7)) * 16), kg = 16B granule 0..7.
// Conflict-free for cp.async stores and ldmatrix reads.
// Property: addr(kg+4) = addr(kg) ^ 64 for kg<4.
__device__ __forceinline__ uint32_t toff(int row, int kg) {
    return (uint32_t)((row << 7) + (((kg ^ (row & 7))) << 4));
}
__device__ __forceinline__ void cpasync16(uint32_t s, const void* g) {
    asm volatile("cp.async.cg.shared.global [%0], [%1], 16;" :: "r"(s), "l"(g) : "memory");
}
template <int N>
__device__ __forceinline__ void cpwait() {
    asm volatile("cp.async.wait_group %0;" :: "n"(N) : "memory");
}
__device__ __forceinline__ void ldm4(uint32_t& r0, uint32_t& r1, uint32_t& r2,
                                     uint32_t& r3, uint32_t a) {
    asm volatile("ldmatrix.sync.aligned.m8n8.x4.shared.b16 {%0,%1,%2,%3}, [%4];"
                 : "=r"(r0), "=r"(r1), "=r"(r2), "=r"(r3) : "r"(a));
}
__device__ __forceinline__ void mma16816(float* c, const uint32_t* a, const uint32_t* b) {
    asm volatile(
        "mma.sync.aligned.m16n8k16.row.col.f32.f16.f16.f32 "
        "{%0,%1,%2,%3}, {%4,%5,%6,%7}, {%8,%9}, {%0,%1,%2,%3};"
        : "+f"(c[0]), "+f"(c[1]), "+f"(c[2]), "+f"(c[3])
        : "r"(a[0]), "r"(a[1]), "r"(a[2]), "r"(a[3]), "r"(b[0]), "r"(b[1]));
}
__device__ __forceinline__ float sqrt_ap(float x) { float r; asm("sqrt.approx.f32 %0,%1;" : "=f"(r) : "f"(x)); return r; }
__device__ __forceinline__ float rcp_ap(float x)  { float r; asm("rcp.approx.f32 %0,%1;"  : "=f"(r) : "f"(x)); return r; }

// ---------------------------------------------------------------------------
// CTA tile 128(n) x 128(m), 8 warps 2(n) x 4(m), warp tile 64x32 (R12 core).
// K = 128 in 2 slices of 64 halfs. Stage = {Ahi 16K, Bhi 16K, Blo 16K} = 48 KB.
// Persistent CTA: tiles from atomic ticket; next tile's slices prefetched
// behind current compute; epilogue overlaps next tile's cp.async.
// ---------------------------------------------------------------------------
#define STG 49152
#define OB_HI 16384
#define OB_LO 32768
#define SMEM_TOTAL (2 * STG + 16)

__global__ __launch_bounds__(256, 2)
void simgemm(float* __restrict__ out) {
    extern __shared__ __align__(1024) char sm[];
    uint32_t sb = s2u(sm);
    int* nxt_sh = (int*)(sm + 2 * STG);
    const int tid = threadIdx.x, lane = tid & 31, w = tid >> 5;
    const int wm = w & 1, wn = w >> 1;      // wm: n-dir (2), wn: m-dir (4)

    // ldmatrix offsets for kk=0,1; kk=2,3 via ^64  (tile-independent)
    uint32_t aoff[4][2], boff[2][2];
    {
        int ar = (lane & 7) + ((lane >> 3) & 1) * 8;
        int akg = lane >> 4;
#pragma unroll
        for (int mi = 0; mi < 4; mi++)
#pragma unroll
            for (int kk = 0; kk < 2; kk++)
                aoff[mi][kk] = toff(wm * 64 + mi * 16 + ar, kk * 2 + akg);
        int br = (lane & 7) + (lane >> 4) * 8;
        int bkg = (lane >> 3) & 1;
#pragma unroll
        for (int nip = 0; nip < 2; nip++)
#pragma unroll
            for (int kk = 0; kk < 2; kk++)
                boff[nip][kk] = toff(wn * 32 + nip * 16 + br, kk * 2 + bkg);
    }

    // issue 64-half K-slice s of tile rows (aR, bR) into stage
    auto issue = [&](int aR, int bR, int s, int stage) {
        const __half* gah = g_hiS + (size_t)aR * CC + s * 64;
        const __half* gbh = g_hiT + (size_t)bR * CC + s * 64;
        const __half* gbl = g_loT + (size_t)bR * CC + s * 64;
        uint32_t st = sb + stage * STG;
#pragma unroll
        for (int j = 0; j < 4; j++) {
            int g = tid + j * 256;
            int row = g >> 3, kg = g & 7;
            uint32_t o = toff(row, kg);
            size_t go = (size_t)row * CC + kg * 8;
            cpasync16(st + o,         gah + go);
            cpasync16(st + OB_HI + o, gbh + go);
            cpasync16(st + OB_LO + o, gbl + go);
        }
        asm volatile("cp.async.commit_group;" ::: "memory");
    };

    float acc[4][4][4];
    auto compute = [&](int stage) {
        uint32_t st = sb + stage * STG;
#pragma unroll
        for (int kk = 0; kk < 4; kk++) {
            const uint32_t x = (kk & 2) ? 64u : 0u;
            const int k2 = kk & 1;
            uint32_t bf[4][2], a[4][4];
#pragma unroll
            for (int nip = 0; nip < 2; nip++)
                ldm4(bf[nip * 2][0], bf[nip * 2][1], bf[nip * 2 + 1][0],
                     bf[nip * 2 + 1][1], st + OB_HI + (boff[nip][k2] ^ x));
#pragma unroll
            for (int mi = 0; mi < 4; mi++)
                ldm4(a[mi][0], a[mi][1], a[mi][2], a[mi][3],
                     st + (aoff[mi][k2] ^ x));
#pragma unroll
            for (int mi = 0; mi < 4; mi++)
#pragma unroll
                for (int ni = 0; ni < 4; ni++)
                    mma16816(acc[mi][ni], a[mi], bf[ni]);
#pragma unroll
            for (int nip = 0; nip < 2; nip++)
                ldm4(bf[nip * 2][0], bf[nip * 2][1], bf[nip * 2 + 1][0],
                     bf[nip * 2 + 1][1], st + OB_LO + (boff[nip][k2] ^ x));
#pragma unroll
            for (int mi = 0; mi < 4; mi++)
#pragma unroll
                for (int ni = 0; ni < 4; ni++)
                    mma16816(acc[mi][ni], a[mi], bf[ni]);
        }
    };

    // tile id decode: bm = t&15 (fastest -> shared A tile in L2), bn, b
    int cur = blockIdx.x;
    int bmc = cur & 15, bnc = (cur >> 4) & 15, bc = cur >> 8;
    int aR = bc * NN + bnc * 128, bR = bc * NN + bmc * 128;

    issue(aR, bR, 0, 0);
    issue(aR, bR, 1, 1);

    const int q = lane >> 2;
    const int mp = (lane & 3) * 2;

    while (true) {
        if (tid == 0) *nxt_sh = atomicAdd(&g_ctr, 1);

#pragma unroll
        for (int i = 0; i < 4; i++)
#pragma unroll
            for (int j = 0; j < 4; j++)
#pragma unroll
                for (int k = 0; k < 4; k++) acc[i][j][k] = 0.0f;

        cpwait<1>(); __syncthreads();        // slice (cur,0) ready; nxt published
        compute(0);
        __syncthreads();                     // stage 0 free

        int nxt = *nxt_sh;
        bool hasn = (nxt < NTILE);
        int nbm = nxt & 15, nbn = (nxt >> 4) & 15, nbb = nxt >> 8;
        int naR = nbb * NN + nbn * 128, nbR = nbb * NN + nbm * 128;
        if (hasn) issue(naR, nbR, 0, 0);

        if (hasn) { cpwait<1>(); } else { cpwait<0>(); }
        __syncthreads();                     // slice (cur,1) ready
        compute(1);
        __syncthreads();                     // stage 1 free
        if (hasn) issue(naR, nbR, 1, 1);

        // ---- epilogue for cur (overlaps next tile's cp.async) ----
#pragma unroll
        for (int mi = 0; mi < 4; mi++) {
            int n0 = bnc * 128 + wm * 64 + mi * 16 + q;
            float2 ns0 = g_nS[bc * NN + n0];
            float2 ns1 = g_nS[bc * NN + n0 + 8];
            float* r0 = out + (((size_t)(bc * NN + n0)) * NN) * 2;
            float* r1 = out + (((size_t)(bc * NN + n0 + 8)) * NN) * 2;
#pragma unroll
            for (int ni = 0; ni < 4; ni++) {
                int m0 = bmc * 128 + wn * 32 + ni * 8 + mp;
                float2 nt0 = g_nT[bc * NN + m0];
                float2 nt1 = g_nT[bc * NN + m0 + 1];
                const float* cc = acc[mi][ni];

                float cs00 = cc[0] * ns0.y * nt0.y;
                float cs01 = cc[1] * ns0.y * nt1.y;
                float cs10 = cc[2] * ns1.y * nt0.y;
                float cs11 = cc[3] * ns1.y * nt1.y;
                float fd00 = rcp_ap(1.0f + sqrt_ap(fmaxf(ns0.x + nt0.x - 2.0f * cc[0], 0.0f)));
                float fd01 = rcp_ap(1.0f + sqrt_ap(fmaxf(ns0.x + nt1.x - 2.0f * cc[1], 0.0f)));
                float fd10 = rcp_ap(1.0f + sqrt_ap(fmaxf(ns1.x + nt0.x - 2.0f * cc[2], 0.0f)));
                float fd11 = rcp_ap(1.0f + sqrt_ap(fmaxf(ns1.x + nt1.x - 2.0f * cc[3], 0.0f)));

                *(float4*)(r0 + (size_t)m0 * 2) = make_float4(cs00, fd00, cs01, fd01);
                *(float4*)(r1 + (size_t)m0 * 2) = make_float4(cs10, fd10, cs11, fd11);
            }
        }

        if (!hasn) break;
        bmc = nbm; bnc = nbn; bc = nbb;
    }
}

// ---------------------------------------------------------------------------
extern "C" void kernel_launch(void* const* d_in, const int* in_sizes, int n_in,
                              void* d_out, int out_size) {
    const float* src = (const float*)d_in[0];
    const float* tgt = (const float*)d_in[1];
    float* out = (float*)d_out;
    (void)in_sizes; (void)n_in; (void)out_size;

    cudaFuncSetAttribute(simgemm, cudaFuncAttributeMaxDynamicSharedMemorySize,
                         SMEM_TOTAL);
    prep<<<dim3(1024, 2, 1), 256>>>(src, tgt);
    simgemm<<<NBLK, 256, SMEM_TOTAL>>>(out);
}